// round 1
// baseline (speedup 1.0000x reference)
#include <cuda_runtime.h>
#include <cuda_bf16.h>

#define WARPS_PER_BLOCK 8
#define THREADS (WARPS_PER_BLOCK * 32)
#define NUM_BLOCKS 2048   // 16384 warps -> 8 rows per warp at N=131072

__global__ __launch_bounds__(THREADS)
void silk_nnue_kernel(const int*   __restrict__ x,
                      const float* __restrict__ emb,
                      const float* __restrict__ W2,
                      const float* __restrict__ b2,
                      const float* __restrict__ W3,
                      const float* __restrict__ b3,
                      const float* __restrict__ W4,
                      float*       __restrict__ out,
                      int nrows)
{
    // Padded weight tiles: row stride 132 (resp. 68) floats => per-lane bank
    // advance of 4, so a 32-lane LDS.128 sweep is conflict-free.
    __shared__ float sW2[32 * 132];
    __shared__ float sW3[32 * 68];
    __shared__ float sb2[32], sb3[32], sW4[64];
    __shared__ float sh[WARPS_PER_BLOCK][128];   // per-warp h vector
    __shared__ float sa[WARPS_PER_BLOCK][64];    // per-warp CReLU vector

    const int tid = threadIdx.x;

    // Cooperative weight staging (amortized over 64 rows per block)
    for (int i = tid; i < 32 * 128; i += THREADS)
        sW2[(i >> 7) * 132 + (i & 127)] = W2[i];
    for (int i = tid; i < 32 * 64; i += THREADS)
        sW3[(i >> 6) * 68 + (i & 63)] = W3[i];
    if (tid < 32)        sb2[tid]      = b2[tid];
    else if (tid < 64)   sb3[tid - 32] = b3[tid - 32];
    else if (tid < 128)  sW4[tid - 64] = W4[tid - 64];
    __syncthreads();

    const int lane = tid & 31;
    const int w    = tid >> 5;

    const float bias2 = sb2[lane];
    const float bias3 = sb3[lane];
    const float w4lo  = sW4[lane];
    const float w4hi  = sW4[lane + 32];

    float* shw = sh[w];
    float* saw = sa[w];
    const float4* emb4  = (const float4*)emb;
    const float4* wrow2 = (const float4*)(sW2 + lane * 132); // 528B offset, 16B aligned
    const float4* wrow3 = (const float4*)(sW3 + lane * 68);  // 272B offset, 16B aligned

    const int gwarp  = blockIdx.x * WARPS_PER_BLOCK + w;
    const int nwarps = gridDim.x * WARPS_PER_BLOCK;

    for (int row = gwarp; row < nrows; row += nwarps) {
        // Each lane holds one of the 32 per-row indices (only 0..28 are used).
        int xi = x[row * 32 + lane];

        // Gather-sum: 29 independent coalesced 512B loads -> high MLP.
        float4 acc = make_float4(0.f, 0.f, 0.f, 0.f);
        #pragma unroll
        for (int j = 0; j < 29; ++j) {
            int idx = __shfl_sync(0xffffffffu, xi, j);
            float4 v = __ldg(emb4 + (size_t)idx * 32 + lane);
            acc.x += v.x; acc.y += v.y; acc.z += v.z; acc.w += v.w;
        }
        acc.x = fmaxf(acc.x, 0.f);
        acc.y = fmaxf(acc.y, 0.f);
        acc.z = fmaxf(acc.z, 0.f);
        acc.w = fmaxf(acc.w, 0.f);

        __syncwarp();                       // WAR: prior iteration readers done
        ((float4*)shw)[lane] = acc;         // STS.128, conflict-free
        __syncwarp();

        // Layer 2: h2[lane] = b2[lane] + sum_k h[k] * W2[lane][k]
        float h2 = bias2;
        #pragma unroll
        for (int s = 0; s < 32; ++s) {
            float4 hv = ((const float4*)shw)[s];  // broadcast LDS.128
            float4 wv = wrow2[s];                 // conflict-free LDS.128
            h2 = fmaf(wv.x, hv.x, h2);
            h2 = fmaf(wv.y, hv.y, h2);
            h2 = fmaf(wv.z, hv.z, h2);
            h2 = fmaf(wv.w, hv.w, h2);
        }

        // CReLU: a = [relu(h2) | relu(-h2)]
        float alo = fmaxf(h2, 0.f);
        float ahi = fmaxf(-h2, 0.f);
        __syncwarp();
        saw[lane]      = alo;
        saw[lane + 32] = ahi;
        __syncwarp();

        // Layer 3: h3[lane] = b3[lane] + sum_k a[k] * W3[lane][k]
        float h3 = bias3;
        #pragma unroll
        for (int s = 0; s < 16; ++s) {
            float4 av = ((const float4*)saw)[s];
            float4 wv = wrow3[s];
            h3 = fmaf(wv.x, av.x, h3);
            h3 = fmaf(wv.y, av.y, h3);
            h3 = fmaf(wv.z, av.z, h3);
            h3 = fmaf(wv.w, av.w, h3);
        }

        // Layer 4: out = sum_k [relu(h3)|relu(-h3)][k] * W4[k] -> warp reduce
        float blo = fmaxf(h3, 0.f);
        float bhi = fmaxf(-h3, 0.f);
        float part = fmaf(w4lo, blo, w4hi * bhi);
        #pragma unroll
        for (int off = 16; off; off >>= 1)
            part += __shfl_xor_sync(0xffffffffu, part, off);

        if (lane == 0) out[row] = part;
    }
}

extern "C" void kernel_launch(void* const* d_in, const int* in_sizes, int n_in,
                              void* d_out, int out_size)
{
    const int*   x   = (const int*)  d_in[0];
    const float* emb = (const float*)d_in[1];
    const float* W2  = (const float*)d_in[2];
    const float* b2  = (const float*)d_in[3];
    const float* W3  = (const float*)d_in[4];
    const float* b3  = (const float*)d_in[5];
    const float* W4  = (const float*)d_in[6];
    float* out = (float*)d_out;

    int nrows = in_sizes[0] / 32;

    silk_nnue_kernel<<<NUM_BLOCKS, THREADS>>>(x, emb, W2, b2, W3, b3, W4, out, nrows);
}

// round 2
// speedup vs baseline: 1.5997x; 1.5997x over previous
#include <cuda_runtime.h>
#include <cuda_fp16.h>

#define WARPS_PER_BLOCK 8
#define THREADS (WARPS_PER_BLOCK * 32)
#define NUM_BLOCKS 2048
#define R 4                      // rows per warp-iteration (weight-LDS amortization)

#define EMB_ELEMS (7424 * 128)
__device__ __half g_emb_h[EMB_ELEMS];   // fp16 repacked embedding table (1.9 MB)

__global__ void cvt_emb_kernel(const float* __restrict__ emb, int n)
{
    int i = blockIdx.x * blockDim.x + threadIdx.x;
    if (i < n) g_emb_h[i] = __float2half(emb[i]);
}

__global__ __launch_bounds__(THREADS)
void silk_nnue_kernel(const int*   __restrict__ x,
                      const float* __restrict__ W2,
                      const float* __restrict__ b2,
                      const float* __restrict__ W3,
                      const float* __restrict__ b3,
                      const float* __restrict__ W4,
                      float*       __restrict__ out,
                      int nrows)
{
    // Padded weight tiles: stride 132/68 floats => lane bank-advance 4,
    // conflict-free 32-lane LDS.128 sweeps.
    __shared__ float sW2[32 * 132];
    __shared__ float sW3[32 * 68];
    __shared__ float sb2[32], sb3[32], sW4[64];
    __shared__ float sh[WARPS_PER_BLOCK][R * 128];  // h vectors; reused for CReLU

    const int tid = threadIdx.x;

    for (int i = tid; i < 32 * 128; i += THREADS)
        sW2[(i >> 7) * 132 + (i & 127)] = W2[i];
    for (int i = tid; i < 32 * 64; i += THREADS)
        sW3[(i >> 6) * 68 + (i & 63)] = W3[i];
    if (tid < 32)        sb2[tid]      = b2[tid];
    else if (tid < 64)   sb3[tid - 32] = b3[tid - 32];
    else if (tid < 128)  sW4[tid - 64] = W4[tid - 64];
    __syncthreads();

    const int lane = tid & 31;
    const int w    = tid >> 5;

    const float bias2 = sb2[lane];
    const float bias3 = sb3[lane];
    const float w4lo  = sW4[lane];
    const float w4hi  = sW4[lane + 32];

    float* shw = sh[w];
    const uint2*  embh2 = (const uint2*)g_emb_h;            // 4 halves / lane
    const float4* wrow2 = (const float4*)(sW2 + lane * 132);
    const float4* wrow3 = (const float4*)(sW3 + lane * 68);

    const int gwarp   = blockIdx.x * WARPS_PER_BLOCK + w;
    const int nwarps  = gridDim.x * WARPS_PER_BLOCK;
    const int ngroups = (nrows + R - 1) / R;

    for (int g = gwarp; g < ngroups; g += nwarps) {
        const int row0 = g * R;

        // Lane l holds index slot l of each of the R rows.
        int xi[R];
        #pragma unroll
        for (int r = 0; r < R; ++r) {
            int row = row0 + r;
            xi[r] = (row < nrows) ? x[row * 32 + lane] : 0;
        }

        // Gather-sum: 29*R independent coalesced 256B fp16 loads (high MLP).
        float4 acc[R];
        #pragma unroll
        for (int r = 0; r < R; ++r) acc[r] = make_float4(0.f, 0.f, 0.f, 0.f);

        #pragma unroll
        for (int j = 0; j < 29; ++j) {
            #pragma unroll
            for (int r = 0; r < R; ++r) {
                int idx = __shfl_sync(0xffffffffu, xi[r], j);
                uint2 v = __ldg(embh2 + (size_t)idx * 32 + lane);
                float2 lo = __half22float2(*(const __half2*)&v.x);
                float2 hi = __half22float2(*(const __half2*)&v.y);
                acc[r].x += lo.x; acc[r].y += lo.y;
                acc[r].z += hi.x; acc[r].w += hi.y;
            }
        }

        __syncwarp();   // WAR vs previous iteration's readers
        #pragma unroll
        for (int r = 0; r < R; ++r) {
            float4 a = acc[r];
            a.x = fmaxf(a.x, 0.f); a.y = fmaxf(a.y, 0.f);
            a.z = fmaxf(a.z, 0.f); a.w = fmaxf(a.w, 0.f);
            ((float4*)(shw + r * 128))[lane] = a;
        }
        __syncwarp();

        // Layer 2: one weight LDS.128 serves all R rows.
        float h2[R];
        #pragma unroll
        for (int r = 0; r < R; ++r) h2[r] = bias2;
        #pragma unroll
        for (int s = 0; s < 32; ++s) {
            float4 wv = wrow2[s];
            #pragma unroll
            for (int r = 0; r < R; ++r) {
                float4 hv = ((const float4*)(shw + r * 128))[s];  // broadcast
                h2[r] = fmaf(wv.x, hv.x, h2[r]);
                h2[r] = fmaf(wv.y, hv.y, h2[r]);
                h2[r] = fmaf(wv.z, hv.z, h2[r]);
                h2[r] = fmaf(wv.w, hv.w, h2[r]);
            }
        }

        // CReLU into the same per-warp region (h no longer needed).
        __syncwarp();
        #pragma unroll
        for (int r = 0; r < R; ++r) {
            shw[r * 64 + lane]      = fmaxf(h2[r], 0.f);
            shw[r * 64 + lane + 32] = fmaxf(-h2[r], 0.f);
        }
        __syncwarp();

        // Layer 3.
        float h3[R];
        #pragma unroll
        for (int r = 0; r < R; ++r) h3[r] = bias3;
        #pragma unroll
        for (int s = 0; s < 16; ++s) {
            float4 wv = wrow3[s];
            #pragma unroll
            for (int r = 0; r < R; ++r) {
                float4 av = ((const float4*)(shw + r * 64))[s];   // broadcast
                h3[r] = fmaf(wv.x, av.x, h3[r]);
                h3[r] = fmaf(wv.y, av.y, h3[r]);
                h3[r] = fmaf(wv.z, av.z, h3[r]);
                h3[r] = fmaf(wv.w, av.w, h3[r]);
            }
        }

        // Layer 4 + warp reduction per row.
        float part[R];
        #pragma unroll
        for (int r = 0; r < R; ++r) {
            float blo = fmaxf(h3[r], 0.f);
            float bhi = fmaxf(-h3[r], 0.f);
            part[r] = fmaf(w4lo, blo, w4hi * bhi);
            #pragma unroll
            for (int off = 16; off; off >>= 1)
                part[r] += __shfl_xor_sync(0xffffffffu, part[r], off);
        }

        if (lane == 0) {
            if (row0 + R <= nrows) {
                *(float4*)(out + row0) = make_float4(part[0], part[1], part[2], part[3]);
            } else {
                for (int r = 0; r < R && row0 + r < nrows; ++r) out[row0 + r] = part[r];
            }
        }
    }
}

extern "C" void kernel_launch(void* const* d_in, const int* in_sizes, int n_in,
                              void* d_out, int out_size)
{
    const int*   x   = (const int*)  d_in[0];
    const float* emb = (const float*)d_in[1];
    const float* W2  = (const float*)d_in[2];
    const float* b2  = (const float*)d_in[3];
    const float* W3  = (const float*)d_in[4];
    const float* b3  = (const float*)d_in[5];
    const float* W4  = (const float*)d_in[6];
    float* out = (float*)d_out;

    int nemb  = in_sizes[1];
    int nrows = in_sizes[0] / 32;

    cvt_emb_kernel<<<(nemb + 511) / 512, 512>>>(emb, nemb);
    silk_nnue_kernel<<<NUM_BLOCKS, THREADS>>>(x, W2, b2, W3, b3, W4, out, nrows);
}